// round 4
// baseline (speedup 1.0000x reference)
#include <cuda_runtime.h>
#include <stdint.h>
#include <math.h>

// ---------------------------------------------------------------------------
// Problem constants (B=1)
// ---------------------------------------------------------------------------
#define T_SEQ 2048
#define D_MODEL 4096
#define KV_DIM 1024
#define HEAD_DIM 128
#define N_HEADS 32
#define N_KV_HEADS 8

// GEMM tiling (tf32 tensor-core path)
#define BM 128
#define BN 128
#define BK 32
#define BKP 36            // padded k-stride in smem (u32)
#define NTHREADS 256

// Flash smem layout (bytes)
#define SM_QS 0
#define SM_KP 73728
#define SM_VS 147456
#define SM_RMAX 165888
#define SM_RSUM 166912
#define SM_FLASH_TOTAL 167936

// ---------------------------------------------------------------------------
// Scratch (static device globals; no runtime allocation)
// ---------------------------------------------------------------------------
__device__ float g_q[T_SEQ * D_MODEL];                 // 32 MB
__device__ float g_k[T_SEQ * KV_DIM];                  // 8 MB
__device__ float g_v[T_SEQ * KV_DIM];                  // 8 MB
__device__ float g_y[T_SEQ * D_MODEL];                 // 32 MB

// ---------------------------------------------------------------------------
// tf32 helpers
// ---------------------------------------------------------------------------
__device__ __forceinline__ uint32_t f2tf(float f) {
    uint32_t u;
    asm("cvt.rna.tf32.f32 %0, %1;" : "=r"(u) : "f"(f));
    return u;
}

// k-column permutation within each 8-group: col(k) = (k&~7) + 2*(k&3) + ((k>>2)&1)
__device__ __forceinline__ int kperm(int k) {
    return (k & ~7) + 2 * (k & 3) + ((k >> 2) & 1);
}

// ---------------------------------------------------------------------------
// Core mma tile: 8 warps, warp_m in [0,4), warp_n in [0,2).
// Each warp: 32(M) x 64(N). acc[2][8][4].
// ---------------------------------------------------------------------------
__device__ __forceinline__ void mma_bk(const uint32_t (*As)[BKP], const uint32_t (*Bs)[BKP],
                                       int warp_m, int warp_n, int lane,
                                       float acc[2][8][4])
{
    const int g = lane >> 2;
    const int t = lane & 3;
#pragma unroll
    for (int kk = 0; kk < BK; kk += 8) {
        uint32_t a[2][4];
#pragma unroll
        for (int i = 0; i < 2; ++i) {
            int r0 = warp_m * 32 + i * 16 + g;
            uint2 lo = *(const uint2*)&As[r0][kk + 2 * t];      // (k=t, k=t+4)
            uint2 hi = *(const uint2*)&As[r0 + 8][kk + 2 * t];
            a[i][0] = lo.x; a[i][1] = hi.x; a[i][2] = lo.y; a[i][3] = hi.y;
        }
#pragma unroll
        for (int j = 0; j < 8; ++j) {
            int n0 = warp_n * 64 + j * 8 + g;
            uint2 bb = *(const uint2*)&Bs[n0][kk + 2 * t];       // (k=t, k=t+4)
#pragma unroll
            for (int i = 0; i < 2; ++i) {
                asm volatile(
                    "mma.sync.aligned.m16n8k8.row.col.f32.tf32.tf32.f32 "
                    "{%0,%1,%2,%3}, {%4,%5,%6,%7}, {%8,%9}, {%0,%1,%2,%3};\n"
                    : "+f"(acc[i][j][0]), "+f"(acc[i][j][1]),
                      "+f"(acc[i][j][2]), "+f"(acc[i][j][3])
                    : "r"(a[i][0]), "r"(a[i][1]), "r"(a[i][2]), "r"(a[i][3]),
                      "r"(bb.x), "r"(bb.y));
            }
        }
    }
}

// ---------------------------------------------------------------------------
// Tile fetch (global -> regs) and store (regs -> smem with cvt + permute)
// ---------------------------------------------------------------------------
__device__ __forceinline__ void fetch_kcontig(const float* __restrict__ src, int ld,
                                              int k0, float4* r, int tid)
{
#pragma unroll
    for (int it = 0; it < 4; ++it) {
        int idx = tid + it * NTHREADS;     // 0..1023
        int row = idx >> 3;                // 0..127
        int kl  = (idx & 7) * 4;           // 0..28
        r[it] = *(const float4*)(src + (size_t)row * ld + k0 + kl);
    }
}

__device__ __forceinline__ void store_kcontig(const float4* r, uint32_t (*dst)[BKP], int tid)
{
#pragma unroll
    for (int it = 0; it < 4; ++it) {
        int idx = tid + it * NTHREADS;
        int row = idx >> 3;
        int kl  = (idx & 7) * 4;
        int base = kl & ~7;
        int bit  = (kl >> 2) & 1;
        dst[row][base + bit + 0] = f2tf(r[it].x);
        dst[row][base + bit + 2] = f2tf(r[it].y);
        dst[row][base + bit + 4] = f2tf(r[it].z);
        dst[row][base + bit + 6] = f2tf(r[it].w);
    }
}

__device__ __forceinline__ void fetch_ncontig(const float* __restrict__ src, int ld,
                                              int k0, float4* r, int tid)
{
#pragma unroll
    for (int it = 0; it < 4; ++it) {
        int idx = tid + it * NTHREADS;
        int krow = idx >> 5;               // 0..31
        int nc   = (idx & 31) * 4;         // 0..124
        r[it] = *(const float4*)(src + (size_t)(k0 + krow) * ld + nc);
    }
}

__device__ __forceinline__ void store_ncontig_T(const float4* r, uint32_t (*dst)[BKP], int tid)
{
#pragma unroll
    for (int it = 0; it < 4; ++it) {
        int idx = tid + it * NTHREADS;
        int krow = idx >> 5;
        int nc   = (idx & 31) * 4;
        int col = kperm(krow);
        dst[nc + 0][col] = f2tf(r[it].x);
        dst[nc + 1][col] = f2tf(r[it].y);
        dst[nc + 2][col] = f2tf(r[it].z);
        dst[nc + 3][col] = f2tf(r[it].w);
    }
}

__device__ __forceinline__ void store_acc(float* __restrict__ C, int ldc,
                                          int row_base, int col_base,
                                          int warp_m, int warp_n, int lane,
                                          float acc[2][8][4], float scale)
{
    const int g = lane >> 2;
    const int t = lane & 3;
#pragma unroll
    for (int i = 0; i < 2; ++i) {
#pragma unroll
        for (int j = 0; j < 8; ++j) {
            int r = row_base + warp_m * 32 + i * 16 + g;
            int c = col_base + warp_n * 64 + j * 8 + t * 2;
            float2 v0 = make_float2(acc[i][j][0] * scale, acc[i][j][1] * scale);
            float2 v1 = make_float2(acc[i][j][2] * scale, acc[i][j][3] * scale);
            *(float2*)(C + (size_t)r * ldc + c) = v0;
            *(float2*)(C + (size_t)(r + 8) * ldc + c) = v1;
        }
    }
}

// ---------------------------------------------------------------------------
// GEMM NT: C[M,N] = A[M,K] * B[N,K]^T  (both K-contiguous), prefetched
// ---------------------------------------------------------------------------
__global__ __launch_bounds__(NTHREADS)
void gemm_tf32_nt(const float* __restrict__ A, const float* __restrict__ B,
                  float* __restrict__ C, int K, int lda, int ldb, int ldc)
{
    __shared__ uint32_t As[BM][BKP];
    __shared__ uint32_t Bs[BN][BKP];

    const int tid = threadIdx.x;
    const int lane = tid & 31;
    const int wid = tid >> 5;
    const int warp_m = wid & 3;
    const int warp_n = wid >> 2;

    const float* Ab = A + (size_t)blockIdx.y * BM * lda;
    const float* Bb = B + (size_t)blockIdx.x * BN * ldb;

    float acc[2][8][4];
#pragma unroll
    for (int i = 0; i < 2; ++i)
#pragma unroll
        for (int j = 0; j < 8; ++j)
#pragma unroll
            for (int r = 0; r < 4; ++r) acc[i][j][r] = 0.f;

    float4 ra[4], rb[4];
    fetch_kcontig(Ab, lda, 0, ra, tid);
    fetch_kcontig(Bb, ldb, 0, rb, tid);

    for (int k0 = 0; k0 < K; k0 += BK) {
        store_kcontig(ra, As, tid);
        store_kcontig(rb, Bs, tid);
        __syncthreads();
        if (k0 + BK < K) {
            fetch_kcontig(Ab, lda, k0 + BK, ra, tid);
            fetch_kcontig(Bb, ldb, k0 + BK, rb, tid);
        }
        mma_bk(As, Bs, warp_m, warp_n, lane, acc);
        __syncthreads();
    }

    store_acc(C, ldc, blockIdx.y * BM, blockIdx.x * BN, warp_m, warp_n, lane, acc, 1.0f);
}

// ---------------------------------------------------------------------------
// Fused flash attention (tf32 mma, online softmax).
// grid = (T/128, N_HEADS). block = 256. One CTA: 128 q-rows of one head.
// ---------------------------------------------------------------------------
__global__ __launch_bounds__(NTHREADS)
void flash_attn(const float* __restrict__ Q, const float* __restrict__ Kg,
                const float* __restrict__ Vg, float* __restrict__ Y)
{
    extern __shared__ char sm[];
    uint32_t (*Qs)[BM][BKP] = (uint32_t (*)[BM][BKP])(sm + SM_QS);   // [4][128][36]
    uint32_t (*KP)[BM][BKP] = (uint32_t (*)[BM][BKP])(sm + SM_KP);   // [4][128][36] K tile then P tile
    uint32_t (*Vs)[BKP]     = (uint32_t (*)[BKP])(sm + SM_VS);       // [128][36]
    float* red_max = (float*)(sm + SM_RMAX);                          // [2][128]
    float* red_sum = (float*)(sm + SM_RSUM);                          // [2][128]

    const int qb = blockIdx.x;
    const int h  = blockIdx.y;
    const int q0 = qb * BM;

    const int tid = threadIdx.x;
    const int lane = tid & 31;
    const int wid = tid >> 5;
    const int warp_m = wid & 3;
    const int warp_n = wid >> 2;
    const int g = lane >> 2;
    const int t = lane & 3;

    const float scale = 0.08838834764831845f;   // 1/sqrt(128)

    // Stage Q once: rows q0..q0+127, head slice, 4 d-chunks
    {
        const float* Qb = Q + (size_t)q0 * D_MODEL + (size_t)h * HEAD_DIM;
        float4 ra[4];
#pragma unroll
        for (int c = 0; c < 4; ++c) {
            fetch_kcontig(Qb, D_MODEL, c * BK, ra, tid);
            store_kcontig(ra, Qs[c], tid);
        }
    }

    float m_r[4], l_r[4];
#pragma unroll
    for (int r = 0; r < 4; ++r) { m_r[r] = -1e30f; l_r[r] = 0.f; }

    float acc_o[2][8][4];
#pragma unroll
    for (int i = 0; i < 2; ++i)
#pragma unroll
        for (int j = 0; j < 8; ++j)
#pragma unroll
            for (int r = 0; r < 4; ++r) acc_o[i][j][r] = 0.f;

    const float* Kb = Kg + (size_t)(h >> 2) * HEAD_DIM;
    const float* Vb = Vg + (size_t)(h >> 2) * HEAD_DIM;

    for (int kb = 0; kb <= qb; ++kb) {
        __syncthreads();   // previous AV mma / Q stage complete before KP overwrite
        {
            const float* Kt = Kb + (size_t)kb * BM * KV_DIM;
            float4 ra[4];
#pragma unroll
            for (int c = 0; c < 4; ++c) {
                fetch_kcontig(Kt, KV_DIM, c * BK, ra, tid);
                store_kcontig(ra, KP[c], tid);
            }
        }
        __syncthreads();

        // ---- S = Q . K^T over 4 d-chunks ----
        float acc_s[2][8][4];
#pragma unroll
        for (int i = 0; i < 2; ++i)
#pragma unroll
            for (int j = 0; j < 8; ++j)
#pragma unroll
                for (int r = 0; r < 4; ++r) acc_s[i][j][r] = 0.f;
#pragma unroll
        for (int c = 0; c < 4; ++c)
            mma_bk(Qs[c], KP[c], warp_m, warp_n, lane, acc_s);

        // ---- scale + causal mask (diagonal block only) ----
        const bool diag = (kb == qb);
#pragma unroll
        for (int i = 0; i < 2; ++i) {
            int r0 = warp_m * 32 + i * 16 + g;
#pragma unroll
            for (int j = 0; j < 8; ++j) {
                int ct = warp_n * 64 + j * 8 + t * 2;
                float s0 = acc_s[i][j][0] * scale;
                float s1 = acc_s[i][j][1] * scale;
                float s2 = acc_s[i][j][2] * scale;
                float s3 = acc_s[i][j][3] * scale;
                if (diag) {
                    if (ct > r0)     s0 = -1e30f;
                    if (ct + 1 > r0) s1 = -1e30f;
                    if (ct > r0 + 8)     s2 = -1e30f;
                    if (ct + 1 > r0 + 8) s3 = -1e30f;
                }
                acc_s[i][j][0] = s0; acc_s[i][j][1] = s1;
                acc_s[i][j][2] = s2; acc_s[i][j][3] = s3;
            }
        }

        // ---- row max ----
        float rmax[4];
#pragma unroll
        for (int i = 0; i < 2; ++i) {
            float m0 = -1e30f, m1 = -1e30f;
#pragma unroll
            for (int j = 0; j < 8; ++j) {
                m0 = fmaxf(m0, fmaxf(acc_s[i][j][0], acc_s[i][j][1]));
                m1 = fmaxf(m1, fmaxf(acc_s[i][j][2], acc_s[i][j][3]));
            }
            rmax[i * 2 + 0] = m0;
            rmax[i * 2 + 1] = m1;
        }
#pragma unroll
        for (int r = 0; r < 4; ++r) {
            rmax[r] = fmaxf(rmax[r], __shfl_xor_sync(0xffffffffu, rmax[r], 1));
            rmax[r] = fmaxf(rmax[r], __shfl_xor_sync(0xffffffffu, rmax[r], 2));
        }
        if (t == 0) {
#pragma unroll
            for (int r = 0; r < 4; ++r) {
                int row = warp_m * 32 + (r >> 1) * 16 + g + (r & 1) * 8;
                red_max[warp_n * 128 + row] = rmax[r];
            }
        }
        __syncthreads();

        float m_new[4], alpha[4];
#pragma unroll
        for (int r = 0; r < 4; ++r) {
            int row = warp_m * 32 + (r >> 1) * 16 + g + (r & 1) * 8;
            float bm = fmaxf(red_max[row], red_max[128 + row]);
            m_new[r] = fmaxf(m_r[r], bm);
            alpha[r] = __expf(m_r[r] - m_new[r]);
        }

        // ---- p = exp(s - m_new), row sums ----
        float rsum[4] = {0.f, 0.f, 0.f, 0.f};
#pragma unroll
        for (int i = 0; i < 2; ++i) {
#pragma unroll
            for (int j = 0; j < 8; ++j) {
                float p0 = __expf(acc_s[i][j][0] - m_new[i * 2 + 0]);
                float p1 = __expf(acc_s[i][j][1] - m_new[i * 2 + 0]);
                float p2 = __expf(acc_s[i][j][2] - m_new[i * 2 + 1]);
                float p3 = __expf(acc_s[i][j][3] - m_new[i * 2 + 1]);
                acc_s[i][j][0] = p0; acc_s[i][j][1] = p1;
                acc_s[i][j][2] = p2; acc_s[i][j][3] = p3;
                rsum[i * 2 + 0] += p0 + p1;
                rsum[i * 2 + 1] += p2 + p3;
            }
        }
#pragma unroll
        for (int r = 0; r < 4; ++r) {
            rsum[r] += __shfl_xor_sync(0xffffffffu, rsum[r], 1);
            rsum[r] += __shfl_xor_sync(0xffffffffu, rsum[r], 2);
        }
        if (t == 0) {
#pragma unroll
            for (int r = 0; r < 4; ++r) {
                int row = warp_m * 32 + (r >> 1) * 16 + g + (r & 1) * 8;
                red_sum[warp_n * 128 + row] = rsum[r];
            }
        }

        // rescale O and l while sums land
#pragma unroll
        for (int i = 0; i < 2; ++i)
#pragma unroll
            for (int j = 0; j < 8; ++j) {
                acc_o[i][j][0] *= alpha[i * 2 + 0];
                acc_o[i][j][1] *= alpha[i * 2 + 0];
                acc_o[i][j][2] *= alpha[i * 2 + 1];
                acc_o[i][j][3] *= alpha[i * 2 + 1];
            }
        __syncthreads();
#pragma unroll
        for (int r = 0; r < 4; ++r) {
            int row = warp_m * 32 + (r >> 1) * 16 + g + (r & 1) * 8;
            float bs = red_sum[row] + red_sum[128 + row];
            l_r[r] = l_r[r] * alpha[r] + bs;
            m_r[r] = m_new[r];
        }

        // ---- store P into KP (K tile is dead now) ----
#pragma unroll
        for (int i = 0; i < 2; ++i) {
            int r0 = warp_m * 32 + i * 16 + g;
#pragma unroll
            for (int j = 0; j < 8; ++j) {
                int ct = warp_n * 64 + j * 8 + t * 2;
                int c = ct >> 5;
                int col0 = kperm(ct & 31);
                int col1 = kperm((ct + 1) & 31);
                KP[c][r0][col0]     = f2tf(acc_s[i][j][0]);
                KP[c][r0][col1]     = f2tf(acc_s[i][j][1]);
                KP[c][r0 + 8][col0] = f2tf(acc_s[i][j][2]);
                KP[c][r0 + 8][col1] = f2tf(acc_s[i][j][3]);
            }
        }

        // ---- O += P . V over 4 token-chunks ----
#pragma unroll
        for (int c = 0; c < 4; ++c) {
            __syncthreads();   // P stores visible; previous chunk's mma done with Vs
            float4 rb[4];
            fetch_ncontig(Vb, KV_DIM, kb * BM + c * BK, rb, tid);
            store_ncontig_T(rb, Vs, tid);
            __syncthreads();
            mma_bk(KP[c], Vs, warp_m, warp_n, lane, acc_o);
        }
    }

    // ---- epilogue: O /= l, write to Y[tok][h*128 + d] ----
    float inv[4];
#pragma unroll
    for (int r = 0; r < 4; ++r) inv[r] = 1.f / l_r[r];

#pragma unroll
    for (int i = 0; i < 2; ++i) {
#pragma unroll
        for (int j = 0; j < 8; ++j) {
            int r = q0 + warp_m * 32 + i * 16 + g;
            int c = h * HEAD_DIM + warp_n * 64 + j * 8 + t * 2;
            float2 v0 = make_float2(acc_o[i][j][0] * inv[i * 2 + 0],
                                    acc_o[i][j][1] * inv[i * 2 + 0]);
            float2 v1 = make_float2(acc_o[i][j][2] * inv[i * 2 + 1],
                                    acc_o[i][j][3] * inv[i * 2 + 1]);
            *(float2*)(Y + (size_t)r * D_MODEL + c) = v0;
            *(float2*)(Y + (size_t)(r + 8) * D_MODEL + c) = v1;
        }
    }
}

// ---------------------------------------------------------------------------
// RoPE over q (32 heads) and k (8 heads), interleaved pairs.
// ---------------------------------------------------------------------------
__global__ __launch_bounds__(256)
void rope_kernel(float* __restrict__ q, float* __restrict__ k,
                 const float* __restrict__ cosp, const float* __restrict__ sinp)
{
    const int idx = blockIdx.x * blockDim.x + threadIdx.x;
    const int qpairs = T_SEQ * (D_MODEL / 2);
    const int kpairs = T_SEQ * (KV_DIM / 2);
    if (idx < qpairs) {
        int t = idx / (D_MODEL / 2);
        int p = idx % (D_MODEL / 2);
        int i = p & 63;
        float c = cosp[t * 64 + i];
        float s = sinp[t * 64 + i];
        float* ptr = q + (size_t)t * D_MODEL + p * 2;
        float x1 = ptr[0], x2 = ptr[1];
        ptr[0] = x1 * c - x2 * s;
        ptr[1] = x1 * s + x2 * c;
    } else if (idx < qpairs + kpairs) {
        int r = idx - qpairs;
        int t = r / (KV_DIM / 2);
        int p = r % (KV_DIM / 2);
        int i = p & 63;
        float c = cosp[t * 64 + i];
        float s = sinp[t * 64 + i];
        float* ptr = k + (size_t)t * KV_DIM + p * 2;
        float x1 = ptr[0], x2 = ptr[1];
        ptr[0] = x1 * c - x2 * s;
        ptr[1] = x1 * s + x2 * c;
    }
}

// ---------------------------------------------------------------------------
// Launch
// ---------------------------------------------------------------------------
extern "C" void kernel_launch(void* const* d_in, const int* in_sizes, int n_in,
                              void* d_out, int out_size)
{
    const float* x    = (const float*)d_in[0];
    const float* cosp = (const float*)d_in[1];
    const float* sinp = (const float*)d_in[2];
    const float* wq   = (const float*)d_in[3];
    const float* wk   = (const float*)d_in[4];
    const float* wv   = (const float*)d_in[5];
    const float* wo   = (const float*)d_in[6];
    float* out = (float*)d_out;

    float *q, *k, *v, *y;
    cudaGetSymbolAddress((void**)&q,  g_q);
    cudaGetSymbolAddress((void**)&k,  g_k);
    cudaGetSymbolAddress((void**)&v,  g_v);
    cudaGetSymbolAddress((void**)&y,  g_y);

    cudaFuncSetAttribute(flash_attn, cudaFuncAttributeMaxDynamicSharedMemorySize,
                         SM_FLASH_TOTAL);

    dim3 blk(NTHREADS);

    gemm_tf32_nt<<<dim3(D_MODEL / BN, T_SEQ / BM), blk>>>(x, wq, q, D_MODEL, D_MODEL, D_MODEL, D_MODEL);
    gemm_tf32_nt<<<dim3(KV_DIM / BN, T_SEQ / BM), blk>>>(x, wk, k, D_MODEL, D_MODEL, D_MODEL, KV_DIM);
    gemm_tf32_nt<<<dim3(KV_DIM / BN, T_SEQ / BM), blk>>>(x, wv, v, D_MODEL, D_MODEL, D_MODEL, KV_DIM);

    {
        int total = T_SEQ * (D_MODEL / 2) + T_SEQ * (KV_DIM / 2);
        rope_kernel<<<(total + 255) / 256, 256>>>(q, k, cosp, sinp);
    }

    flash_attn<<<dim3(T_SEQ / BM, N_HEADS), blk, SM_FLASH_TOTAL>>>(q, k, v, y);

    gemm_tf32_nt<<<dim3(D_MODEL / BN, T_SEQ / BM), blk>>>(y, wo, out, D_MODEL, D_MODEL, D_MODEL, D_MODEL);
}

// round 6
// speedup vs baseline: 2.0686x; 2.0686x over previous
#include <cuda_runtime.h>
#include <stdint.h>
#include <math.h>

// ---------------------------------------------------------------------------
// Problem constants (B=1)
// ---------------------------------------------------------------------------
#define T_SEQ 2048
#define D_MODEL 4096
#define KV_DIM 1024
#define HEAD_DIM 128
#define N_HEADS 32
#define N_KV_HEADS 8

#define BK 32
#define ROWB 144              // bytes per smem row (36 u32, padded)
#define NTHREADS 256
#define STAGES 3
#define STAGE_BYTES 55296     // (128+256)*144
#define SMEM_TOTAL (STAGES * STAGE_BYTES)   // 165888

// ---------------------------------------------------------------------------
// Scratch
// ---------------------------------------------------------------------------
__device__ float g_q[T_SEQ * D_MODEL];
__device__ float g_k[T_SEQ * KV_DIM];
__device__ float g_v[T_SEQ * KV_DIM];
__device__ float g_y[T_SEQ * D_MODEL];
__device__ float g_scores[134217728];   // 512 MB

// ---------------------------------------------------------------------------
// Helpers
// ---------------------------------------------------------------------------
__device__ __forceinline__ uint32_t f2tf(float f) {
    uint32_t u;
    asm("cvt.rna.tf32.f32 %0, %1;" : "=r"(u) : "f"(f));
    return u;
}

__device__ __forceinline__ uint32_t smem_u32(const void* p) {
    uint32_t a;
    asm("{ .reg .u64 t; cvta.to.shared.u64 t, %1; cvt.u32.u64 %0, t; }"
        : "=r"(a) : "l"(p));
    return a;
}

__device__ __forceinline__ void cp16(uint32_t dst, const void* src) {
    asm volatile("cp.async.cg.shared.global [%0], [%1], 16;" :: "r"(dst), "l"(src));
}
#define CP_COMMIT() asm volatile("cp.async.commit_group;" ::: "memory")
#define CP_WAIT(n)  asm volatile("cp.async.wait_group %0;" :: "n"(n) : "memory")

// Stage ROWS x 32 fp32 tile (K-contiguous) raw into smem [row][k], row stride 144B.
template<int ROWS>
__device__ __forceinline__ void cpstage(uint32_t dst, const float* __restrict__ src,
                                        int ld, int k0, int tid)
{
#pragma unroll
    for (int it = 0; it < ROWS / 32; ++it) {
        int c = tid + it * NTHREADS;
        int row = c >> 3;
        int ci = c & 7;
        cp16(dst + row * ROWB + ci * 16, src + (size_t)row * ld + k0 + ci * 4);
    }
}

// ---------------------------------------------------------------------------
// 64x64 warp mma over one BK=32 tile. acc[4][8][4].
// As: [Mrows][36] u32 (raw fp32 if CA, tf32 if !CA). Bs: [Nrows][36].
// ---------------------------------------------------------------------------
template<bool CA, bool CB>
__device__ __forceinline__ void mma64(const uint32_t* __restrict__ As,
                                      const uint32_t* __restrict__ Bs,
                                      int wm, int wn, int lane,
                                      float acc[4][8][4])
{
    const int g = lane >> 2;
    const int t = lane & 3;
#pragma unroll
    for (int kk = 0; kk < BK; kk += 8) {
        uint32_t a[4][4];
#pragma unroll
        for (int i = 0; i < 4; ++i) {
            int r0 = wm * 64 + i * 16 + g;
            uint32_t a0 = As[r0 * 36 + kk + t];
            uint32_t a1 = As[(r0 + 8) * 36 + kk + t];
            uint32_t a2 = As[r0 * 36 + kk + t + 4];
            uint32_t a3 = As[(r0 + 8) * 36 + kk + t + 4];
            if (CA) {
                a0 = f2tf(__uint_as_float(a0)); a1 = f2tf(__uint_as_float(a1));
                a2 = f2tf(__uint_as_float(a2)); a3 = f2tf(__uint_as_float(a3));
            }
            a[i][0] = a0; a[i][1] = a1; a[i][2] = a2; a[i][3] = a3;
        }
#pragma unroll
        for (int j = 0; j < 8; ++j) {
            int n0 = wn * 64 + j * 8 + g;
            uint32_t b0 = Bs[n0 * 36 + kk + t];
            uint32_t b1 = Bs[n0 * 36 + kk + t + 4];
            if (CB) {
                b0 = f2tf(__uint_as_float(b0)); b1 = f2tf(__uint_as_float(b1));
            }
#pragma unroll
            for (int i = 0; i < 4; ++i) {
                asm volatile(
                    "mma.sync.aligned.m16n8k8.row.col.f32.tf32.tf32.f32 "
                    "{%0,%1,%2,%3}, {%4,%5,%6,%7}, {%8,%9}, {%0,%1,%2,%3};\n"
                    : "+f"(acc[i][j][0]), "+f"(acc[i][j][1]),
                      "+f"(acc[i][j][2]), "+f"(acc[i][j][3])
                    : "r"(a[i][0]), "r"(a[i][1]), "r"(a[i][2]), "r"(a[i][3]),
                      "r"(b0), "r"(b1));
            }
        }
    }
}

__device__ __forceinline__ void store_acc64(float* __restrict__ C, int ldc,
                                            int row_base, int col_base,
                                            int wm, int wn, int lane,
                                            float acc[4][8][4], float scale)
{
    const int g = lane >> 2;
    const int t = lane & 3;
#pragma unroll
    for (int i = 0; i < 4; ++i) {
#pragma unroll
        for (int j = 0; j < 8; ++j) {
            int r = row_base + wm * 64 + i * 16 + g;
            int c = col_base + wn * 64 + j * 8 + t * 2;
            float2 v0 = make_float2(acc[i][j][0] * scale, acc[i][j][1] * scale);
            float2 v1 = make_float2(acc[i][j][2] * scale, acc[i][j][3] * scale);
            *(float2*)(C + (size_t)r * ldc + c) = v0;
            *(float2*)(C + (size_t)(r + 8) * ldc + c) = v1;
        }
    }
}

// ---------------------------------------------------------------------------
// GEMM NT core: C[128,256] tile = A[128,K] * B[256,K]^T, cp.async 3-stage.
// ---------------------------------------------------------------------------
__device__ __forceinline__ void gemm_nt_core(const float* Ab, const float* Bb,
                                             float* C, int K, int lda, int ldb,
                                             int ldc, int row_base, int col_base,
                                             float scale, char* sm, int tid)
{
    const uint32_t sb = smem_u32(sm);
    const int lane = tid & 31;
    const int wid = tid >> 5;
    const int wm = wid & 1;
    const int wn = wid >> 1;

    float acc[4][8][4];
#pragma unroll
    for (int i = 0; i < 4; ++i)
#pragma unroll
        for (int j = 0; j < 8; ++j)
#pragma unroll
            for (int r = 0; r < 4; ++r) acc[i][j][r] = 0.f;

    const int NK = K / BK;

    cpstage<128>(sb, Ab, lda, 0, tid);
    cpstage<256>(sb + 18432, Bb, ldb, 0, tid);
    CP_COMMIT();
    cpstage<128>(sb + STAGE_BYTES, Ab, lda, BK, tid);
    cpstage<256>(sb + STAGE_BYTES + 18432, Bb, ldb, BK, tid);
    CP_COMMIT();
    CP_WAIT(1);
    __syncthreads();

    for (int kt = 0; kt < NK; ++kt) {
        const int s = kt % STAGES;
        const uint32_t* As = (const uint32_t*)(sm + s * STAGE_BYTES);
        const uint32_t* Bs = (const uint32_t*)(sm + s * STAGE_BYTES + 18432);
        mma64<true, true>(As, Bs, wm, wn, lane, acc);
        if (kt + 2 < NK) {
            const int ns = (kt + 2) % STAGES;
            cpstage<128>(sb + ns * STAGE_BYTES, Ab, lda, (kt + 2) * BK, tid);
            cpstage<256>(sb + ns * STAGE_BYTES + 18432, Bb, ldb, (kt + 2) * BK, tid);
            CP_COMMIT();
            CP_WAIT(1);
        } else if (kt + 1 < NK) {
            CP_WAIT(0);
        }
        __syncthreads();
    }

    store_acc64(C, ldc, row_base, col_base, wm, wn, lane, acc, scale);
}

__global__ __launch_bounds__(NTHREADS)
void gemm_tf32_nt2(const float* __restrict__ A, const float* __restrict__ B,
                   float* __restrict__ C, int K, int lda, int ldb, int ldc)
{
    extern __shared__ char sm[];
    gemm_nt_core(A + (size_t)blockIdx.y * 128 * lda,
                 B + (size_t)blockIdx.x * 256 * ldb,
                 C, K, lda, ldb, ldc,
                 blockIdx.y * 128, blockIdx.x * 256, 1.0f, sm, threadIdx.x);
}

// k and v projections in one launch (z picks weight/output)
__global__ __launch_bounds__(NTHREADS)
void gemm_tf32_kv(const float* __restrict__ X,
                  const float* __restrict__ Wk, const float* __restrict__ Wv,
                  float* __restrict__ Ko, float* __restrict__ Vo)
{
    extern __shared__ char sm[];
    const float* B = (blockIdx.z == 0) ? Wk : Wv;
    float* C = (blockIdx.z == 0) ? Ko : Vo;
    gemm_nt_core(X + (size_t)blockIdx.y * 128 * D_MODEL,
                 B + (size_t)blockIdx.x * 256 * D_MODEL,
                 C, D_MODEL, D_MODEL, D_MODEL, KV_DIM,
                 blockIdx.y * 128, blockIdx.x * 256, 1.0f, sm, threadIdx.x);
}

// ---------------------------------------------------------------------------
// Scores: S[h][q][c] tile 128x256, K=128, causal block skip.
// ---------------------------------------------------------------------------
__global__ __launch_bounds__(NTHREADS)
void gemm_scores2(const float* __restrict__ Q, const float* __restrict__ Kt,
                  float* __restrict__ S, float scale)
{
    const int h = blockIdx.z;
    const int q0 = blockIdx.y * 128;
    const int c0 = blockIdx.x * 256;
    if (c0 > q0 + 127) return;
    extern __shared__ char sm[];
    gemm_nt_core(Q + (size_t)q0 * D_MODEL + (size_t)h * HEAD_DIM,
                 Kt + (size_t)c0 * KV_DIM + (size_t)(h >> 2) * HEAD_DIM,
                 S + (size_t)h * T_SEQ * T_SEQ, HEAD_DIM, D_MODEL, KV_DIM, T_SEQ,
                 q0, c0, scale, sm, threadIdx.x);
}

// ---------------------------------------------------------------------------
// AV: Y tile 256x128. P via cp.async (raw), V transposed+tf32 via regs.
// ---------------------------------------------------------------------------
__device__ __forceinline__ void fetch_v(const float* __restrict__ src, int k0,
                                        float4* r, int tid)
{
    int kq = tid >> 5;              // 0..7 -> k rows kq*4..+3
    int nc = (tid & 31) * 4;        // cols
#pragma unroll
    for (int m = 0; m < 4; ++m)
        r[m] = *(const float4*)(src + (size_t)(k0 + kq * 4 + m) * KV_DIM + nc);
}

__device__ __forceinline__ void store_v(const float4* r, uint32_t* buf, int tid)
{
    int kq = tid >> 5;
    int nc = (tid & 31) * 4;
#pragma unroll
    for (int m = 0; m < 4; ++m) {
        uint4 w;
        w.x = f2tf((&r[0].x)[m]);
        w.y = f2tf((&r[1].x)[m]);
        w.z = f2tf((&r[2].x)[m]);
        w.w = f2tf((&r[3].x)[m]);
        *(uint4*)(buf + (nc + m) * 36 + kq * 4) = w;
    }
}

__global__ __launch_bounds__(NTHREADS)
void gemm_av2(const float* __restrict__ Attn, const float* __restrict__ V,
              float* __restrict__ Y)
{
    extern __shared__ char sm[];
    const uint32_t sb = smem_u32(sm);
    const int h = blockIdx.z;
    const int q0 = blockIdx.y * 256;
    const int tid = threadIdx.x;
    const int lane = tid & 31;
    const int wid = tid >> 5;
    const int wm = wid & 3;          // 4 x 64 = 256 rows
    const int wn = wid >> 2;         // 2 x 64 = 128 cols

    const float* Ab = Attn + (size_t)h * T_SEQ * T_SEQ + (size_t)q0 * T_SEQ;
    const float* Vb = V + (size_t)(h >> 2) * HEAD_DIM;
    float* C = Y + (size_t)h * HEAD_DIM;

    const int NK = (q0 + 256) / BK;      // >= 8

    float acc[4][8][4];
#pragma unroll
    for (int i = 0; i < 4; ++i)
#pragma unroll
        for (int j = 0; j < 8; ++j)
#pragma unroll
            for (int r = 0; r < 4; ++r) acc[i][j][r] = 0.f;

    float4 rv[4];

    // prologue: P t0,t1 via cp.async; V t0 staged; V t1 fetched
    cpstage<256>(sb, Ab, T_SEQ, 0, tid);
    CP_COMMIT();
    cpstage<256>(sb + STAGE_BYTES, Ab, T_SEQ, BK, tid);
    CP_COMMIT();
    fetch_v(Vb, 0, rv, tid);
    store_v(rv, (uint32_t*)(sm + 36864), tid);
    CP_WAIT(1);
    __syncthreads();
    fetch_v(Vb, BK, rv, tid);

    for (int kt = 0; kt < NK; ++kt) {
        const int s = kt % STAGES;
        const uint32_t* Ps = (const uint32_t*)(sm + s * STAGE_BYTES);
        const uint32_t* Vs = (const uint32_t*)(sm + s * STAGE_BYTES + 36864);
        mma64<true, false>(Ps, Vs, wm, wn, lane, acc);
        if (kt + 2 < NK) {
            const int ns = (kt + 2) % STAGES;
            cpstage<256>(sb + ns * STAGE_BYTES, Ab, T_SEQ, (kt + 2) * BK, tid);
            CP_COMMIT();
        }
        if (kt + 1 < NK) {
            const int ws = (kt + 1) % STAGES;
            store_v(rv, (uint32_t*)(sm + ws * STAGE_BYTES + 36864), tid);
        }
        if (kt + 2 < NK) CP_WAIT(1);
        else if (kt + 1 < NK) CP_WAIT(0);
        __syncthreads();
        if (kt + 2 < NK) fetch_v(Vb, (kt + 2) * BK, rv, tid);
    }

    store_acc64(C, D_MODEL, q0, 0, wm, wn, lane, acc, 1.0f);
}

// ---------------------------------------------------------------------------
// Causal softmax; zero-fill to end of 256-wide diagonal block (AV BM=256).
// ---------------------------------------------------------------------------
__inline__ __device__ float warp_max(float v) {
#pragma unroll
    for (int o = 16; o; o >>= 1) v = fmaxf(v, __shfl_xor_sync(0xffffffffu, v, o));
    return v;
}
__inline__ __device__ float warp_sum(float v) {
#pragma unroll
    for (int o = 16; o; o >>= 1) v += __shfl_xor_sync(0xffffffffu, v, o);
    return v;
}

__global__ __launch_bounds__(256)
void softmax_causal(float* __restrict__ sc)
{
    const int row = blockIdx.x & (T_SEQ - 1);
    float* p = sc + (size_t)blockIdx.x * T_SEQ;
    const int len = row + 1;
    const int fill_end = (row | 255) + 1;
    const int tid = threadIdx.x;
    const int lane = tid & 31;
    const int wid = tid >> 5;
    __shared__ float red[8];

    float m = -3.4e38f;
    for (int j = tid; j < len; j += 256) m = fmaxf(m, p[j]);
    m = warp_max(m);
    if (lane == 0) red[wid] = m;
    __syncthreads();
    if (wid == 0) {
        float x = (lane < 8) ? red[lane] : -3.4e38f;
        x = warp_max(x);
        if (lane == 0) red[0] = x;
    }
    __syncthreads();
    m = red[0];
    __syncthreads();

    float s = 0.f;
    for (int j = tid; j < len; j += 256) {
        float e = __expf(p[j] - m);
        p[j] = e;
        s += e;
    }
    s = warp_sum(s);
    if (lane == 0) red[wid] = s;
    __syncthreads();
    if (wid == 0) {
        float x = (lane < 8) ? red[lane] : 0.f;
        x = warp_sum(x);
        if (lane == 0) red[0] = x;
    }
    __syncthreads();
    const float inv = 1.f / red[0];

    for (int j = tid; j < len; j += 256) p[j] *= inv;
    for (int j = len + tid; j < fill_end; j += 256) p[j] = 0.f;
}

// ---------------------------------------------------------------------------
// RoPE
// ---------------------------------------------------------------------------
__global__ __launch_bounds__(256)
void rope_kernel(float* __restrict__ q, float* __restrict__ k,
                 const float* __restrict__ cosp, const float* __restrict__ sinp)
{
    const int idx = blockIdx.x * blockDim.x + threadIdx.x;
    const int qpairs = T_SEQ * (D_MODEL / 2);
    const int kpairs = T_SEQ * (KV_DIM / 2);
    if (idx < qpairs) {
        int t = idx / (D_MODEL / 2);
        int p = idx % (D_MODEL / 2);
        int i = p & 63;
        float c = cosp[t * 64 + i];
        float s = sinp[t * 64 + i];
        float* ptr = q + (size_t)t * D_MODEL + p * 2;
        float x1 = ptr[0], x2 = ptr[1];
        ptr[0] = x1 * c - x2 * s;
        ptr[1] = x1 * s + x2 * c;
    } else if (idx < qpairs + kpairs) {
        int r = idx - qpairs;
        int t = r / (KV_DIM / 2);
        int p = r % (KV_DIM / 2);
        int i = p & 63;
        float c = cosp[t * 64 + i];
        float s = sinp[t * 64 + i];
        float* ptr = k + (size_t)t * KV_DIM + p * 2;
        float x1 = ptr[0], x2 = ptr[1];
        ptr[0] = x1 * c - x2 * s;
        ptr[1] = x1 * s + x2 * c;
    }
}

// ---------------------------------------------------------------------------
// Launch
// ---------------------------------------------------------------------------
extern "C" void kernel_launch(void* const* d_in, const int* in_sizes, int n_in,
                              void* d_out, int out_size)
{
    const float* x    = (const float*)d_in[0];
    const float* cosp = (const float*)d_in[1];
    const float* sinp = (const float*)d_in[2];
    const float* wq   = (const float*)d_in[3];
    const float* wk   = (const float*)d_in[4];
    const float* wv   = (const float*)d_in[5];
    const float* wo   = (const float*)d_in[6];
    float* out = (float*)d_out;

    float *q, *k, *v, *y, *sc;
    cudaGetSymbolAddress((void**)&q,  g_q);
    cudaGetSymbolAddress((void**)&k,  g_k);
    cudaGetSymbolAddress((void**)&v,  g_v);
    cudaGetSymbolAddress((void**)&y,  g_y);
    cudaGetSymbolAddress((void**)&sc, g_scores);

    cudaFuncSetAttribute(gemm_tf32_nt2, cudaFuncAttributeMaxDynamicSharedMemorySize, SMEM_TOTAL);
    cudaFuncSetAttribute(gemm_tf32_kv,  cudaFuncAttributeMaxDynamicSharedMemorySize, SMEM_TOTAL);
    cudaFuncSetAttribute(gemm_scores2,  cudaFuncAttributeMaxDynamicSharedMemorySize, SMEM_TOTAL);
    cudaFuncSetAttribute(gemm_av2,      cudaFuncAttributeMaxDynamicSharedMemorySize, SMEM_TOTAL);

    dim3 blk(NTHREADS);

    gemm_tf32_nt2<<<dim3(D_MODEL / 256, T_SEQ / 128), blk, SMEM_TOTAL>>>(
        x, wq, q, D_MODEL, D_MODEL, D_MODEL, D_MODEL);
    gemm_tf32_kv<<<dim3(KV_DIM / 256, T_SEQ / 128, 2), blk, SMEM_TOTAL>>>(
        x, wk, wv, k, v);

    {
        int total = T_SEQ * (D_MODEL / 2) + T_SEQ * (KV_DIM / 2);
        rope_kernel<<<(total + 255) / 256, 256>>>(q, k, cosp, sinp);
    }

    const float scale = 0.08838834764831845f;   // 1/sqrt(128)
    gemm_scores2<<<dim3(T_SEQ / 256, T_SEQ / 128, N_HEADS), blk, SMEM_TOTAL>>>(q, k, sc, scale);
    softmax_causal<<<N_HEADS * T_SEQ, 256>>>(sc);
    gemm_av2<<<dim3(1, T_SEQ / 256, N_HEADS), blk, SMEM_TOTAL>>>(sc, v, y);

    gemm_tf32_nt2<<<dim3(D_MODEL / 256, T_SEQ / 128), blk, SMEM_TOTAL>>>(
        y, wo, out, D_MODEL, D_MODEL, D_MODEL, D_MODEL);
}

// round 7
// speedup vs baseline: 2.6766x; 1.2939x over previous
#include <cuda_runtime.h>
#include <stdint.h>
#include <math.h>

// ---------------------------------------------------------------------------
// Problem constants (B=1)
// ---------------------------------------------------------------------------
#define T_SEQ 2048
#define D_MODEL 4096
#define KV_DIM 1024
#define HEAD_DIM 128
#define N_HEADS 32

#define BK 32
#define ROWB 80                 // bytes per fp16 smem row (32 halves + 8 pad)
#define NTHREADS 256
#define STGB 30720              // (128+256) rows * 80 B
#define SMEM_NT (2 * STGB)      // 61440

// AV smem: P 256 rows * 80 = 20480 ; V 32 rows * 272 = 8704
#define VROWB 272
#define AV_STGB (20480 + 8704)  // 29184
#define SMEM_AV (2 * AV_STGB)   // 58368

// ---------------------------------------------------------------------------
// Scratch
// ---------------------------------------------------------------------------
__device__ float g_q[T_SEQ * D_MODEL];
__device__ float g_k[T_SEQ * KV_DIM];
__device__ float g_v[T_SEQ * KV_DIM];
__device__ float g_y[T_SEQ * D_MODEL];
__device__ float g_scores[134217728];          // 512 MB
__device__ float g_invl[N_HEADS * T_SEQ];      // per-row 1/l

// ---------------------------------------------------------------------------
// Helpers
// ---------------------------------------------------------------------------
__device__ __forceinline__ uint32_t smem_u32(const void* p) {
    uint32_t a;
    asm("{ .reg .u64 t; cvta.to.shared.u64 t, %1; cvt.u32.u64 %0, t; }"
        : "=r"(a) : "l"(p));
    return a;
}

// pack two f32 -> f16x2, lo = first arg
__device__ __forceinline__ uint32_t pk(float lo, float hi) {
    uint32_t r;
    asm("cvt.rn.f16x2.f32 %0, %1, %2;" : "=r"(r) : "f"(hi), "f"(lo));
    return r;
}

__device__ __forceinline__ void sts16B(uint32_t addr, uint32_t w0, uint32_t w1,
                                       uint32_t w2, uint32_t w3) {
    asm volatile("st.shared.v4.b32 [%0], {%1,%2,%3,%4};"
                 :: "r"(addr), "r"(w0), "r"(w1), "r"(w2), "r"(w3) : "memory");
}

__device__ __forceinline__ void ldsm4(uint32_t& r0, uint32_t& r1, uint32_t& r2,
                                      uint32_t& r3, uint32_t a) {
    asm volatile("ldmatrix.sync.aligned.m8n8.x4.shared.b16 {%0,%1,%2,%3}, [%4];"
                 : "=r"(r0), "=r"(r1), "=r"(r2), "=r"(r3) : "r"(a));
}
__device__ __forceinline__ void ldsm4t(uint32_t& r0, uint32_t& r1, uint32_t& r2,
                                       uint32_t& r3, uint32_t a) {
    asm volatile("ldmatrix.sync.aligned.m8n8.x4.trans.shared.b16 {%0,%1,%2,%3}, [%4];"
                 : "=r"(r0), "=r"(r1), "=r"(r2), "=r"(r3) : "r"(a));
}

__device__ __forceinline__ void mma16816(float* d, uint32_t a0, uint32_t a1,
                                         uint32_t a2, uint32_t a3,
                                         uint32_t b0, uint32_t b1) {
    asm volatile(
        "mma.sync.aligned.m16n8k16.row.col.f32.f16.f16.f32 "
        "{%0,%1,%2,%3},{%4,%5,%6,%7},{%8,%9},{%0,%1,%2,%3};"
        : "+f"(d[0]), "+f"(d[1]), "+f"(d[2]), "+f"(d[3])
        : "r"(a0), "r"(a1), "r"(a2), "r"(a3), "r"(b0), "r"(b1));
}

// ---------------------------------------------------------------------------
// 64x64 warp fp16 mma over one BK=32 tile (A rows @sa, B rows @sbb, stride 80B)
// ---------------------------------------------------------------------------
__device__ __forceinline__ void mma64h(uint32_t sa, uint32_t sbb, int wm, int wn,
                                       int lane, float acc[4][8][4])
{
    const int sub = lane >> 3, rr = lane & 7;
    const uint32_t loff = ((sub & 1) * 8 + rr) * ROWB + (sub >> 1) * 16;
#pragma unroll
    for (int kk = 0; kk < 2; ++kk) {
        uint32_t a[4][4];
#pragma unroll
        for (int i = 0; i < 4; ++i)
            ldsm4(a[i][0], a[i][1], a[i][2], a[i][3],
                  sa + (wm * 64 + i * 16) * ROWB + kk * 32 + loff);
        uint32_t b[4][4];
#pragma unroll
        for (int jj = 0; jj < 4; ++jj)
            ldsm4(b[jj][0], b[jj][1], b[jj][2], b[jj][3],
                  sbb + (wn * 64 + jj * 16) * ROWB + kk * 32 + loff);
#pragma unroll
        for (int i = 0; i < 4; ++i)
#pragma unroll
            for (int jj = 0; jj < 4; ++jj) {
                mma16816(acc[i][jj * 2],     a[i][0], a[i][1], a[i][2], a[i][3],
                         b[jj][0], b[jj][2]);
                mma16816(acc[i][jj * 2 + 1], a[i][0], a[i][1], a[i][2], a[i][3],
                         b[jj][1], b[jj][3]);
            }
    }
}

__device__ __forceinline__ void store_acc64(float* __restrict__ C, int ldc,
                                            int row_base, int col_base,
                                            int wm, int wn, int lane,
                                            float acc[4][8][4], float scale)
{
    const int g = lane >> 2;
    const int t = lane & 3;
#pragma unroll
    for (int i = 0; i < 4; ++i) {
#pragma unroll
        for (int j = 0; j < 8; ++j) {
            int r = row_base + wm * 64 + i * 16 + g;
            int c = col_base + wn * 64 + j * 8 + t * 2;
            float2 v0 = make_float2(acc[i][j][0] * scale, acc[i][j][1] * scale);
            float2 v1 = make_float2(acc[i][j][2] * scale, acc[i][j][3] * scale);
            *(float2*)(C + (size_t)r * ldc + c) = v0;
            *(float2*)(C + (size_t)(r + 8) * ldc + c) = v1;
        }
    }
}

// ---------------------------------------------------------------------------
// NT staging: A 128 rows + B 256 rows, K-contig fp32 -> fp16 smem
// ---------------------------------------------------------------------------
__device__ __forceinline__ void fetch_nt(const float* __restrict__ A, int lda,
                                         const float* __restrict__ B, int ldb,
                                         int k0, float4* r, int tid)
{
    const int row0 = tid >> 2;
    const int kq = (tid & 3) * 8;
#pragma unroll
    for (int it = 0; it < 2; ++it) {
        const float* s = A + (size_t)(row0 + it * 64) * lda + k0 + kq;
        r[it * 2] = *(const float4*)s;
        r[it * 2 + 1] = *(const float4*)(s + 4);
    }
#pragma unroll
    for (int it = 0; it < 4; ++it) {
        const float* s = B + (size_t)(row0 + it * 64) * ldb + k0 + kq;
        r[4 + it * 2] = *(const float4*)s;
        r[5 + it * 2] = *(const float4*)(s + 4);
    }
}

__device__ __forceinline__ void sts_nt(uint32_t sb, const float4* r, int tid)
{
    const int row0 = tid >> 2;
    const int kb = (tid & 3) * 16;
#pragma unroll
    for (int it = 0; it < 2; ++it) {
        const float4 a = r[it * 2], b = r[it * 2 + 1];
        sts16B(sb + (row0 + it * 64) * ROWB + kb,
               pk(a.x, a.y), pk(a.z, a.w), pk(b.x, b.y), pk(b.z, b.w));
    }
#pragma unroll
    for (int it = 0; it < 4; ++it) {
        const float4 a = r[4 + it * 2], b = r[5 + it * 2];
        sts16B(sb + (128 + row0 + it * 64) * ROWB + kb,
               pk(a.x, a.y), pk(a.z, a.w), pk(b.x, b.y), pk(b.z, b.w));
    }
}

// ---------------------------------------------------------------------------
// NT core: C tile [128,256] = A[128,K] * B[256,K]^T
// ---------------------------------------------------------------------------
__device__ __forceinline__ void gemm_nt_core_h(const float* Ab, const float* Bb,
                                               float* C, int K, int lda, int ldb,
                                               int ldc, int row_base, int col_base,
                                               float scale, char* sm, int tid)
{
    const uint32_t sb = smem_u32(sm);
    const int lane = tid & 31, wid = tid >> 5;
    const int wm = wid & 1, wn = wid >> 1;

    float acc[4][8][4];
#pragma unroll
    for (int i = 0; i < 4; ++i)
#pragma unroll
        for (int j = 0; j < 8; ++j)
#pragma unroll
            for (int r = 0; r < 4; ++r) acc[i][j][r] = 0.f;

    float4 r[12];
    const int NK = K / BK;
    fetch_nt(Ab, lda, Bb, ldb, 0, r, tid);

    for (int kt = 0; kt < NK; ++kt) {
        const uint32_t s = sb + (kt & 1) * STGB;
        sts_nt(s, r, tid);
        __syncthreads();
        if (kt + 1 < NK) fetch_nt(Ab, lda, Bb, ldb, (kt + 1) * BK, r, tid);
        mma64h(s, s + 128 * ROWB, wm, wn, lane, acc);
        __syncthreads();
    }
    store_acc64(C, ldc, row_base, col_base, wm, wn, lane, acc, scale);
}

__global__ __launch_bounds__(NTHREADS)
void gemm_h_nt(const float* __restrict__ A, const float* __restrict__ B,
               float* __restrict__ C, int K, int lda, int ldb, int ldc)
{
    extern __shared__ char sm[];
    gemm_nt_core_h(A + (size_t)blockIdx.y * 128 * lda,
                   B + (size_t)blockIdx.x * 256 * ldb,
                   C, K, lda, ldb, ldc,
                   blockIdx.y * 128, blockIdx.x * 256, 1.0f, sm, threadIdx.x);
}

__global__ __launch_bounds__(NTHREADS)
void gemm_h_kv(const float* __restrict__ X,
               const float* __restrict__ Wk, const float* __restrict__ Wv,
               float* __restrict__ Ko, float* __restrict__ Vo)
{
    extern __shared__ char sm[];
    const float* B = (blockIdx.z == 0) ? Wk : Wv;
    float* C = (blockIdx.z == 0) ? Ko : Vo;
    gemm_nt_core_h(X + (size_t)blockIdx.y * 128 * D_MODEL,
                   B + (size_t)blockIdx.x * 256 * D_MODEL,
                   C, D_MODEL, D_MODEL, D_MODEL, KV_DIM,
                   blockIdx.y * 128, blockIdx.x * 256, 1.0f, sm, threadIdx.x);
}

__global__ __launch_bounds__(NTHREADS)
void gemm_h_scores(const float* __restrict__ Q, const float* __restrict__ Kt,
                   float* __restrict__ S, float scale)
{
    const int h = blockIdx.z;
    const int q0 = blockIdx.y * 128;
    const int c0 = blockIdx.x * 256;
    if (c0 > q0 + 127) return;
    extern __shared__ char sm[];
    gemm_nt_core_h(Q + (size_t)q0 * D_MODEL + (size_t)h * HEAD_DIM,
                   Kt + (size_t)c0 * KV_DIM + (size_t)(h >> 2) * HEAD_DIM,
                   S + (size_t)h * T_SEQ * T_SEQ, HEAD_DIM, D_MODEL, KV_DIM, T_SEQ,
                   q0, c0, scale, sm, threadIdx.x);
}

// ---------------------------------------------------------------------------
// AV kernel: Y tile [256,128] = P[256,kmax] * V[kmax,128]
// P staged fp32->fp16 with *invl; V staged [k][n] and loaded via ldmatrix.trans.
// ---------------------------------------------------------------------------
__device__ __forceinline__ void fetch_p(const float* __restrict__ P, int k0,
                                        float4* r, int tid)
{
    const int row0 = tid >> 2;
    const int kq = (tid & 3) * 8;
#pragma unroll
    for (int it = 0; it < 4; ++it) {
        const float* s = P + (size_t)(row0 + it * 64) * T_SEQ + k0 + kq;
        r[it * 2] = *(const float4*)s;
        r[it * 2 + 1] = *(const float4*)(s + 4);
    }
}

__device__ __forceinline__ void sts_p(uint32_t sb, const float4* r,
                                      const float* inv4, int tid)
{
    const int row0 = tid >> 2;
    const int kb = (tid & 3) * 16;
#pragma unroll
    for (int it = 0; it < 4; ++it) {
        float iv = inv4[it];
        float4 a = r[it * 2], b = r[it * 2 + 1];
        sts16B(sb + (row0 + it * 64) * ROWB + kb,
               pk(a.x * iv, a.y * iv), pk(a.z * iv, a.w * iv),
               pk(b.x * iv, b.y * iv), pk(b.z * iv, b.w * iv));
    }
}

__device__ __forceinline__ void fetch_v(const float* __restrict__ V, int k0,
                                        float4* r, int tid)
{
    const int kr = tid >> 3;             // 0..31
    const int nc = (tid & 7) * 16;       // 0..112
    const float* s = V + (size_t)(k0 + kr) * KV_DIM + nc;
#pragma unroll
    for (int m = 0; m < 4; ++m) r[m] = *(const float4*)(s + m * 4);
}

__device__ __forceinline__ void sts_v(uint32_t vb, const float4* r, int tid)
{
    const int kr = tid >> 3;
    const int nc = (tid & 7) * 16;
    uint32_t addr = vb + kr * VROWB + nc * 2;
    sts16B(addr,      pk(r[0].x, r[0].y), pk(r[0].z, r[0].w),
                      pk(r[1].x, r[1].y), pk(r[1].z, r[1].w));
    sts16B(addr + 16, pk(r[2].x, r[2].y), pk(r[2].z, r[2].w),
                      pk(r[3].x, r[3].y), pk(r[3].z, r[3].w));
}

__global__ __launch_bounds__(NTHREADS)
void gemm_h_av(const float* __restrict__ Attn, const float* __restrict__ V,
               const float* __restrict__ invl, float* __restrict__ Y)
{
    extern __shared__ char sm[];
    const uint32_t sb = smem_u32(sm);
    const int h = blockIdx.z;
    const int q0 = (int)(gridDim.y - 1 - blockIdx.y) * 256;   // heavy-first
    const int tid = threadIdx.x;
    const int lane = tid & 31;
    const int wid = tid >> 5;
    const int wm = wid & 3;          // 4 x 64 = 256 rows
    const int wn = wid >> 2;         // 2 x 64 = 128 cols

    const float* Ab = Attn + (size_t)h * T_SEQ * T_SEQ + (size_t)q0 * T_SEQ;
    const float* Vb = V + (size_t)(h >> 2) * HEAD_DIM;
    float* C = Y + (size_t)h * HEAD_DIM;

    // per-thread invl for the 4 staged P rows
    float inv4[4];
    {
        const int row0 = tid >> 2;
#pragma unroll
        for (int it = 0; it < 4; ++it)
            inv4[it] = invl[h * T_SEQ + q0 + row0 + it * 64];
    }

    const int NK = (q0 + 256) / BK;

    float acc[4][8][4];
#pragma unroll
    for (int i = 0; i < 4; ++i)
#pragma unroll
        for (int j = 0; j < 8; ++j)
#pragma unroll
            for (int r = 0; r < 4; ++r) acc[i][j][r] = 0.f;

    float4 rp[8], rv[4];
    fetch_p(Ab, 0, rp, tid);
    fetch_v(Vb, 0, rv, tid);

    const int sub = lane >> 3, rr = lane & 7;
    const uint32_t poff = ((sub & 1) * 8 + rr) * ROWB + (sub >> 1) * 16;

    for (int kt = 0; kt < NK; ++kt) {
        const uint32_t s = sb + (kt & 1) * AV_STGB;
        sts_p(s, rp, inv4, tid);
        sts_v(s + 20480, rv, tid);
        __syncthreads();
        if (kt + 1 < NK) {
            fetch_p(Ab, (kt + 1) * BK, rp, tid);
            fetch_v(Vb, (kt + 1) * BK, rv, tid);
        }
        const uint32_t vbase = s + 20480;
#pragma unroll
        for (int kk = 0; kk < 2; ++kk) {
            uint32_t a[4][4];
#pragma unroll
            for (int i = 0; i < 4; ++i)
                ldsm4(a[i][0], a[i][1], a[i][2], a[i][3],
                      s + (wm * 64 + i * 16) * ROWB + kk * 32 + poff);
            uint32_t b[4][4];
#pragma unroll
            for (int jj = 0; jj < 4; ++jj)
                ldsm4t(b[jj][0], b[jj][1], b[jj][2], b[jj][3],
                       vbase + (kk * 16 + (sub >> 1) * 8 + rr) * VROWB
                             + (wn * 64 + jj * 16) * 2 + (sub & 1) * 16);
#pragma unroll
            for (int i = 0; i < 4; ++i)
#pragma unroll
                for (int jj = 0; jj < 4; ++jj) {
                    mma16816(acc[i][jj * 2],     a[i][0], a[i][1], a[i][2], a[i][3],
                             b[jj][0], b[jj][2]);
                    mma16816(acc[i][jj * 2 + 1], a[i][0], a[i][1], a[i][2], a[i][3],
                             b[jj][1], b[jj][3]);
                }
        }
        __syncthreads();
    }

    store_acc64(C, D_MODEL, q0, 0, wm, wn, lane, acc, 1.0f);
}

// ---------------------------------------------------------------------------
// Softmax, 2 passes: (1) read -> online (m, l); (2) write exp(x-m), zero-fill.
// invl written per row; final normalization applied in AV staging.
// ---------------------------------------------------------------------------
__global__ __launch_bounds__(256)
void softmax_ml(float* __restrict__ sc, float* __restrict__ invl)
{
    const int row = blockIdx.x & (T_SEQ - 1);
    float* p = sc + (size_t)blockIdx.x * T_SEQ;
    const int len = row + 1;
    const int fill_end = (row | 255) + 1;
    const int tid = threadIdx.x;
    const int lane = tid & 31;
    const int wid = tid >> 5;
    __shared__ float rm[8], rl[8];

    // pass 1: per-thread online (m, l)
    float m = -3.4e38f, l = 0.f;
    for (int j = tid; j < len; j += 256) {
        float x = p[j];
        if (x > m) { l *= __expf(m - x); m = x; }
        l += __expf(x - m);
    }
    // warp reduce (m, l)
#pragma unroll
    for (int o = 16; o; o >>= 1) {
        float mo = __shfl_xor_sync(0xffffffffu, m, o);
        float lo = __shfl_xor_sync(0xffffffffu, l, o);
        float M = fmaxf(m, mo);
        l = l * __expf(m - M) + lo * __expf(mo - M);
        m = M;
    }
    if (lane == 0) { rm[wid] = m; rl[wid] = l; }
    __syncthreads();
    if (wid == 0) {
        float mm = (lane < 8) ? rm[lane] : -3.4e38f;
        float ll = (lane < 8) ? rl[lane] : 0.f;
#pragma unroll
        for (int o = 4; o; o >>= 1) {
            float mo = __shfl_xor_sync(0xffffffffu, mm, o);
            float lo = __shfl_xor_sync(0xffffffffu, ll, o);
            float M = fmaxf(mm, mo);
            ll = ll * __expf(mm - M) + lo * __expf(mo - M);
            mm = M;
        }
        if (lane == 0) { rm[0] = mm; rl[0] = ll; }
    }
    __syncthreads();
    m = rm[0];
    if (tid == 0) invl[blockIdx.x] = 1.f / rl[0];

    // pass 2: exp write + zero fill
    for (int j = tid; j < len; j += 256) p[j] = __expf(p[j] - m);
    for (int j = len + tid; j < fill_end; j += 256) p[j] = 0.f;
}

// ---------------------------------------------------------------------------
// RoPE
// ---------------------------------------------------------------------------
__global__ __launch_bounds__(256)
void rope_kernel(float* __restrict__ q, float* __restrict__ k,
                 const float* __restrict__ cosp, const float* __restrict__ sinp)
{
    const int idx = blockIdx.x * blockDim.x + threadIdx.x;
    const int qpairs = T_SEQ * (D_MODEL / 2);
    const int kpairs = T_SEQ * (KV_DIM / 2);
    if (idx < qpairs) {
        int t = idx / (D_MODEL / 2);
        int p = idx % (D_MODEL / 2);
        int i = p & 63;
        float c = cosp[t * 64 + i];
        float s = sinp[t * 64 + i];
        float* ptr = q + (size_t)t * D_MODEL + p * 2;
        float x1 = ptr[0], x2 = ptr[1];
        ptr[0] = x1 * c - x2 * s;
        ptr[1] = x1 * s + x2 * c;
    } else if (idx < qpairs + kpairs) {
        int r = idx - qpairs;
        int t = r / (KV_DIM / 2);
        int p = r % (KV_DIM / 2);
        int i = p & 63;
        float c = cosp[t * 64 + i];
        float s = sinp[t * 64 + i];
        float* ptr = k + (size_t)t * KV_DIM + p * 2;
        float x1 = ptr[0], x2 = ptr[1];
        ptr[0] = x1 * c - x2 * s;
        ptr[1] = x1 * s + x2 * c;
    }
}

// ---------------------------------------------------------------------------
// Launch
// ---------------------------------------------------------------------------
extern "C" void kernel_launch(void* const* d_in, const int* in_sizes, int n_in,
                              void* d_out, int out_size)
{
    const float* x    = (const float*)d_in[0];
    const float* cosp = (const float*)d_in[1];
    const float* sinp = (const float*)d_in[2];
    const float* wq   = (const float*)d_in[3];
    const float* wk   = (const float*)d_in[4];
    const float* wv   = (const float*)d_in[5];
    const float* wo   = (const float*)d_in[6];
    float* out = (float*)d_out;

    float *q, *k, *v, *y, *sc, *il;
    cudaGetSymbolAddress((void**)&q,  g_q);
    cudaGetSymbolAddress((void**)&k,  g_k);
    cudaGetSymbolAddress((void**)&v,  g_v);
    cudaGetSymbolAddress((void**)&y,  g_y);
    cudaGetSymbolAddress((void**)&sc, g_scores);
    cudaGetSymbolAddress((void**)&il, g_invl);

    cudaFuncSetAttribute(gemm_h_nt,     cudaFuncAttributeMaxDynamicSharedMemorySize, SMEM_NT);
    cudaFuncSetAttribute(gemm_h_kv,     cudaFuncAttributeMaxDynamicSharedMemorySize, SMEM_NT);
    cudaFuncSetAttribute(gemm_h_scores, cudaFuncAttributeMaxDynamicSharedMemorySize, SMEM_NT);
    cudaFuncSetAttribute(gemm_h_av,     cudaFuncAttributeMaxDynamicSharedMemorySize, SMEM_AV);

    dim3 blk(NTHREADS);

    gemm_h_nt<<<dim3(D_MODEL / 256, T_SEQ / 128), blk, SMEM_NT>>>(
        x, wq, q, D_MODEL, D_MODEL, D_MODEL, D_MODEL);
    gemm_h_kv<<<dim3(KV_DIM / 256, T_SEQ / 128, 2), blk, SMEM_NT>>>(
        x, wk, wv, k, v);

    {
        int total = T_SEQ * (D_MODEL / 2) + T_SEQ * (KV_DIM / 2);
        rope_kernel<<<(total + 255) / 256, 256>>>(q, k, cosp, sinp);
    }

    const float scale = 0.08838834764831845f;   // 1/sqrt(128)
    gemm_h_scores<<<dim3(T_SEQ / 256, T_SEQ / 128, N_HEADS), blk, SMEM_NT>>>(q, k, sc, scale);
    softmax_ml<<<N_HEADS * T_SEQ, 256>>>(sc, il);
    gemm_h_av<<<dim3(1, T_SEQ / 256, N_HEADS), blk, SMEM_AV>>>(sc, v, il, y);

    gemm_h_nt<<<dim3(D_MODEL / 256, T_SEQ / 128), blk, SMEM_NT>>>(
        y, wo, out, D_MODEL, D_MODEL, D_MODEL, D_MODEL);
}